// round 14
// baseline (speedup 1.0000x reference)
#include <cuda_runtime.h>
#include <cuda_bf16.h>
#include <cuda_fp16.h>
#include <math.h>
#include <float.h>
#include <stdint.h>

#define N_NODES 50000
#define N_EDGES 800000
#define SLOPE 0.2f

// ---------------- scratch (device globals; no allocation allowed) ----------
__device__ float    g_gl[N_NODES * 128];   // fp16 view (layers 1-2) / fp32 [N,40] (layer 3)
__device__ float    g_gr[N_NODES * 128];
__device__ uint32_t g_hs[N_NODES * 128];   // packed split of hidden h
__device__ uint32_t g_ws[4 * 16384];       // packed splits of Wl1,Wr1,Wl2,Wr2
__device__ uint32_t g_w3s[2 * 8192];       // packed splits of Wl3,Wr3 padded [128,64]
__device__ int      g_deg[N_NODES];
__device__ int      g_off[N_NODES];
__device__ int      g_cur[N_NODES];
__device__ int      g_bsum[64];
__device__ int      g_eidx[N_EDGES];

// ---- bf16 hi/lo split pack -------------------------------------------------
__device__ __forceinline__ uint32_t packsplit(float x) {
    __nv_bfloat16 h = __float2bfloat16(x);
    __nv_bfloat16 l = __float2bfloat16(x - __bfloat162float(h));
    return ((uint32_t)__bfloat16_as_ushort(h) << 16) | (uint32_t)__bfloat16_as_ushort(l);
}

// fused split: blocks 0-63 pack Wl1,Wr1,Wl2,Wr2 into g_ws;
// blocks 64-79 pack Wl3,Wr3 (40 cols, zero-padded to 64) into g_w3s.
__global__ void k_split_w(const float* __restrict__ w0, const float* __restrict__ w1,
                          const float* __restrict__ w2, const float* __restrict__ w3,
                          uint32_t* __restrict__ outp,
                          const float* __restrict__ w3a, const float* __restrict__ w3b,
                          uint32_t* __restrict__ out3) {
    if (blockIdx.x < 64) {
        int i = (blockIdx.x * 256 + threadIdx.x) * 4;
        int sel = i >> 14;
        int o4 = i & 16383;
        const float* w = (sel == 0) ? w0 : (sel == 1) ? w1 : (sel == 2) ? w2 : w3;
        float4 v = *(const float4*)(w + o4);
        uint4 o;
        o.x = packsplit(v.x); o.y = packsplit(v.y);
        o.z = packsplit(v.z); o.w = packsplit(v.w);
        *(uint4*)(outp + i) = o;
    } else {
        int g = (blockIdx.x - 64) * 256 + threadIdx.x;   // 0..4095
        int sel = g >> 11;
        int gg = g & 2047;
        int e0 = gg * 4;
        int k = e0 >> 6, c = e0 & 63;
        const float* w = sel ? w3b : w3a;
        uint32_t o[4];
        #pragma unroll
        for (int j = 0; j < 4; j++) {
            float v = (c + j < 40) ? w[k * 40 + c + j] : 0.f;
            o[j] = packsplit(v);
        }
        *(uint4*)(out3 + sel * 8192 + k * 64 + c) = make_uint4(o[0], o[1], o[2], o[3]);
    }
}

// ================= CSR construction ==========================================
// 4 edges per thread for MLP=4 (ATOMG/REDG return latency overlapped).
__global__ void k_hist(const int4* __restrict__ dst4, int* __restrict__ deg) {
    int i = blockIdx.x * blockDim.x + threadIdx.x;
    if (i >= N_EDGES / 4) return;
    int4 d = __ldg(&dst4[i]);
    atomicAdd(&deg[d.x], 1);
    atomicAdd(&deg[d.y], 1);
    atomicAdd(&deg[d.z], 1);
    atomicAdd(&deg[d.w], 1);
}

__global__ __launch_bounds__(1024) void k_scan_part(
    const int* __restrict__ deg, int* __restrict__ off, int* __restrict__ bsum)
{
    __shared__ int sh[1024];
    int t = threadIdx.x;
    int i = blockIdx.x * 1024 + t;
    int v = (i < N_NODES) ? deg[i] : 0;
    sh[t] = v;
    __syncthreads();
    #pragma unroll
    for (int o = 1; o < 1024; o <<= 1) {
        int u = (t >= o) ? sh[t - o] : 0;
        __syncthreads();
        sh[t] += u;
        __syncthreads();
    }
    if (i < N_NODES) off[i] = sh[t] - v;
    if (t == 1023) bsum[blockIdx.x] = sh[t];
}

__global__ void k_scan_add(int* __restrict__ off, int* __restrict__ cur,
                           const int* __restrict__ bsum)
{
    __shared__ int base_sh;
    int i = blockIdx.x * blockDim.x + threadIdx.x;
    int b = (blockIdx.x * blockDim.x) >> 10;
    if (threadIdx.x == 0) {
        int s = 0;
        for (int j = 0; j < b; j++) s += bsum[j];
        base_sh = s;
    }
    __syncthreads();
    if (i >= N_NODES) return;
    int o = off[i] + base_sh;
    off[i] = o;
    cur[i] = o;
}

__global__ void k_scatter(const int4* __restrict__ src4, const int4* __restrict__ dst4,
                          int* __restrict__ cur, int* __restrict__ eidx)
{
    int i = blockIdx.x * blockDim.x + threadIdx.x;
    if (i >= N_EDGES / 4) return;
    int4 s = __ldg(&src4[i]);
    int4 d = __ldg(&dst4[i]);
    int p0 = atomicAdd(&cur[d.x], 1);
    int p1 = atomicAdd(&cur[d.y], 1);
    int p2 = atomicAdd(&cur[d.z], 1);
    int p3 = atomicAdd(&cur[d.w], 1);
    eidx[p0] = s.x;
    eidx[p1] = s.y;
    eidx[p2] = s.z;
    eidx[p3] = s.w;
}

// ================= tensor-core helpers =======================================
__device__ __forceinline__ uint32_t smem_u32(const void* p) {
    return (uint32_t)__cvta_generic_to_shared(p);
}
__device__ __forceinline__ void ldsm_x4(uint32_t& r0, uint32_t& r1, uint32_t& r2, uint32_t& r3, uint32_t addr) {
    asm volatile("ldmatrix.sync.aligned.m8n8.x4.shared.b16 {%0,%1,%2,%3},[%4];"
                 : "=r"(r0), "=r"(r1), "=r"(r2), "=r"(r3) : "r"(addr));
}
__device__ __forceinline__ void ldsm_x2_t(uint32_t& r0, uint32_t& r1, uint32_t addr) {
    asm volatile("ldmatrix.sync.aligned.m8n8.x2.trans.shared.b16 {%0,%1},[%2];"
                 : "=r"(r0), "=r"(r1) : "r"(addr));
}
__device__ __forceinline__ void mma_bf16c(float* d, const uint32_t* a, const uint32_t* b) {
    asm volatile("mma.sync.aligned.m16n8k16.row.col.f32.bf16.bf16.f32 "
                 "{%0,%1,%2,%3},{%4,%5,%6,%7},{%8,%9},{%0,%1,%2,%3};"
                 : "+f"(d[0]), "+f"(d[1]), "+f"(d[2]), "+f"(d[3])
                 : "r"(a[0]), "r"(a[1]), "r"(a[2]), "r"(a[3]), "r"(b[0]), "r"(b[1]));
}

// ================= TC dual GEMM (layers 1-2), fp16 output ===================
// 2-product error-compensated: ah*wh + al*wh.
template <bool RAW>
__global__ __launch_bounds__(256, 2) void k_gemm_tc2(
    const uint32_t* __restrict__ Ap, const float* __restrict__ Araw,
    const uint32_t* __restrict__ W1p, const uint32_t* __restrict__ W2p,
    __half* __restrict__ C1, __half* __restrict__ C2, int M)
{
    __shared__ __nv_bfloat16 Ah[64][40];
    __shared__ __nv_bfloat16 Al[64][40];
    __shared__ __nv_bfloat16 Wh[32][264];

    const int tid = threadIdx.x, lane = tid & 31, wid = tid >> 5;
    const int wm = wid & 1;
    const int wn = wid >> 1;
    const int r0 = blockIdx.x * 64;

    float d[2][8][4];
    #pragma unroll
    for (int i = 0; i < 2; i++)
        #pragma unroll
        for (int j = 0; j < 8; j++)
            #pragma unroll
            for (int k = 0; k < 4; k++) d[i][j][k] = 0.f;

    for (int kt = 0; kt < 4; kt++) {
        #pragma unroll
        for (int i = 0; i < 2; i++) {
            int idx = tid + i * 256;
            int row = idx >> 3, q = idx & 7;
            if (RAW) {
                float4 v = make_float4(0.f, 0.f, 0.f, 0.f);
                if (r0 + row < M)
                    v = *(const float4*)(Araw + (size_t)(r0 + row) * 128 + kt * 32 + q * 4);
                float ar[4] = {v.x, v.y, v.z, v.w};
                __nv_bfloat16 h[4], lo[4];
                #pragma unroll
                for (int j = 0; j < 4; j++) {
                    h[j] = __float2bfloat16(ar[j]);
                    lo[j] = __float2bfloat16(ar[j] - __bfloat162float(h[j]));
                }
                *(uint2*)&Ah[row][q * 4] = *(uint2*)h;
                *(uint2*)&Al[row][q * 4] = *(uint2*)lo;
            } else {
                uint4 p = make_uint4(0u, 0u, 0u, 0u);
                if (r0 + row < M)
                    p = *(const uint4*)(Ap + (size_t)(r0 + row) * 128 + kt * 32 + q * 4);
                uint2 hi, lo;
                hi.x = __byte_perm(p.x, p.y, 0x7632); hi.y = __byte_perm(p.z, p.w, 0x7632);
                lo.x = __byte_perm(p.x, p.y, 0x5410); lo.y = __byte_perm(p.z, p.w, 0x5410);
                *(uint2*)&Ah[row][q * 4] = hi;
                *(uint2*)&Al[row][q * 4] = lo;
            }
        }
        #pragma unroll
        for (int i = 0; i < 8; i++) {
            int idx = tid + i * 256;
            int k = idx >> 6, q = idx & 63;
            uint4 p = (q < 32)
                ? *(const uint4*)(W1p + (size_t)(kt * 32 + k) * 128 + q * 4)
                : *(const uint4*)(W2p + (size_t)(kt * 32 + k) * 128 + (q - 32) * 4);
            uint2 hi;
            hi.x = __byte_perm(p.x, p.y, 0x7632); hi.y = __byte_perm(p.z, p.w, 0x7632);
            *(uint2*)&Wh[k][q * 4] = hi;
        }
        __syncthreads();

        #pragma unroll
        for (int ph = 0; ph < 2; ph++) {
            const __nv_bfloat16 (*Asm)[40] = (ph == 1) ? Al : Ah;
            #pragma unroll
            for (int k16 = 0; k16 < 2; k16++) {
                uint32_t af[2][4], bfr[8][2];
                #pragma unroll
                for (int mf = 0; mf < 2; mf++) {
                    uint32_t addr = smem_u32(
                        &Asm[wm * 32 + mf * 16 + (lane & 15)][k16 * 16 + (lane >> 4) * 8]);
                    ldsm_x4(af[mf][0], af[mf][1], af[mf][2], af[mf][3], addr);
                }
                #pragma unroll
                for (int nf = 0; nf < 8; nf++) {
                    uint32_t addr = smem_u32(
                        &Wh[k16 * 16 + (lane & 15)][wn * 64 + nf * 8]);
                    ldsm_x2_t(bfr[nf][0], bfr[nf][1], addr);
                }
                #pragma unroll
                for (int mf = 0; mf < 2; mf++)
                    #pragma unroll
                    for (int nf = 0; nf < 8; nf++)
                        mma_bf16c(d[mf][nf], af[mf], bfr[nf]);
            }
        }
        __syncthreads();
    }

    const int g = lane >> 2, t = lane & 3;
    __half* Cp = (wn < 2) ? C1 : C2;
    int cbase = (wn < 2) ? wn * 64 : (wn - 2) * 64;
    #pragma unroll
    for (int mf = 0; mf < 2; mf++) {
        #pragma unroll
        for (int nf = 0; nf < 8; nf++) {
            int row0 = r0 + wm * 32 + mf * 16 + g;
            int col = cbase + nf * 8 + t * 2;
            if (row0 < M)
                *(__half2*)(Cp + (size_t)row0 * 128 + col) =
                    __floats2half2_rn(d[mf][nf][0], d[mf][nf][1]);
            if (row0 + 8 < M)
                *(__half2*)(Cp + (size_t)(row0 + 8) * 128 + col) =
                    __floats2half2_rn(d[mf][nf][2], d[mf][nf][3]);
        }
    }
}

// ================= TC dual GEMM layer 3 (N=40 padded to 64, fp32 out) =======
__global__ __launch_bounds__(256, 2) void k_gemm_tc3(
    const uint32_t* __restrict__ Ap, const uint32_t* __restrict__ W3p,
    float* __restrict__ C1, float* __restrict__ C2, int M)
{
    __shared__ __nv_bfloat16 Ah[64][40];
    __shared__ __nv_bfloat16 Al[64][40];
    __shared__ __nv_bfloat16 Wh[32][136];

    const int tid = threadIdx.x, lane = tid & 31, wid = tid >> 5;
    const int wm = wid & 1;
    const int wn = wid >> 1;
    const int r0 = blockIdx.x * 64;

    float d[2][4][4];
    #pragma unroll
    for (int i = 0; i < 2; i++)
        #pragma unroll
        for (int j = 0; j < 4; j++)
            #pragma unroll
            for (int k = 0; k < 4; k++) d[i][j][k] = 0.f;

    for (int kt = 0; kt < 4; kt++) {
        #pragma unroll
        for (int i = 0; i < 2; i++) {
            int idx = tid + i * 256;
            int row = idx >> 3, q = idx & 7;
            uint4 p = make_uint4(0u, 0u, 0u, 0u);
            if (r0 + row < M)
                p = *(const uint4*)(Ap + (size_t)(r0 + row) * 128 + kt * 32 + q * 4);
            uint2 hi, lo;
            hi.x = __byte_perm(p.x, p.y, 0x7632); hi.y = __byte_perm(p.z, p.w, 0x7632);
            lo.x = __byte_perm(p.x, p.y, 0x5410); lo.y = __byte_perm(p.z, p.w, 0x5410);
            *(uint2*)&Ah[row][q * 4] = hi;
            *(uint2*)&Al[row][q * 4] = lo;
        }
        #pragma unroll
        for (int i = 0; i < 4; i++) {
            int idx = tid + i * 256;
            int k = idx >> 5, q = idx & 31;
            const uint32_t* src = W3p + ((q >= 16) ? 8192 : 0)
                                + (size_t)(kt * 32 + k) * 64 + (q & 15) * 4;
            uint4 p = *(const uint4*)src;
            uint2 hi;
            hi.x = __byte_perm(p.x, p.y, 0x7632); hi.y = __byte_perm(p.z, p.w, 0x7632);
            *(uint2*)&Wh[k][q * 4] = hi;
        }
        __syncthreads();

        #pragma unroll
        for (int ph = 0; ph < 2; ph++) {
            const __nv_bfloat16 (*Asm)[40] = (ph == 1) ? Al : Ah;
            #pragma unroll
            for (int k16 = 0; k16 < 2; k16++) {
                uint32_t af[2][4], bfr[4][2];
                #pragma unroll
                for (int mf = 0; mf < 2; mf++) {
                    uint32_t addr = smem_u32(
                        &Asm[wm * 32 + mf * 16 + (lane & 15)][k16 * 16 + (lane >> 4) * 8]);
                    ldsm_x4(af[mf][0], af[mf][1], af[mf][2], af[mf][3], addr);
                }
                #pragma unroll
                for (int nf = 0; nf < 4; nf++) {
                    uint32_t addr = smem_u32(
                        &Wh[k16 * 16 + (lane & 15)][wn * 32 + nf * 8]);
                    ldsm_x2_t(bfr[nf][0], bfr[nf][1], addr);
                }
                #pragma unroll
                for (int mf = 0; mf < 2; mf++)
                    #pragma unroll
                    for (int nf = 0; nf < 4; nf++)
                        mma_bf16c(d[mf][nf], af[mf], bfr[nf]);
            }
        }
        __syncthreads();
    }

    const int g = lane >> 2, t = lane & 3;
    float* Cp = (wn < 2) ? C1 : C2;
    int cbase = (wn & 1) * 32;
    #pragma unroll
    for (int mf = 0; mf < 2; mf++) {
        #pragma unroll
        for (int nf = 0; nf < 4; nf++) {
            int row0 = r0 + wm * 32 + mf * 16 + g;
            int col = cbase + nf * 8 + t * 2;
            if (col >= 40) continue;
            if (row0 < M)
                *(float2*)(Cp + (size_t)row0 * 40 + col) = make_float2(d[mf][nf][0], d[mf][nf][1]);
            if (row0 + 8 < M)
                *(float2*)(Cp + (size_t)(row0 + 8) * 40 + col) = make_float2(d[mf][nf][2], d[mf][nf][3]);
        }
    }
}

// ================= node aggregation (H=4, F=32), half2 math, 2 edges/warp ===
__global__ __launch_bounds__(256) void k_node_h4(
    const uint4* __restrict__ glh, const uint4* __restrict__ grh,
    const float* __restrict__ att,
    const int* __restrict__ off, const int* __restrict__ deg,
    const int* __restrict__ eidx, uint4* __restrict__ houtp, int mode)
{
    int n = blockIdx.x * 8 + (threadIdx.x >> 5);
    if (n >= N_NODES) return;
    int lane = threadIdx.x & 31;
    int sub = lane >> 4;
    int ll = lane & 15;

    uint4 braw = grh[(size_t)n * 16 + ll];
    __half2 b2[4];
    b2[0] = *(__half2*)&braw.x; b2[1] = *(__half2*)&braw.y;
    b2[2] = *(__half2*)&braw.z; b2[3] = *(__half2*)&braw.w;

    float4 t0 = __ldg((const float4*)att + 2 * ll);
    float4 t1 = __ldg((const float4*)att + 2 * ll + 1);
    __half2 t2[4];
    t2[0] = __floats2half2_rn(t0.x, t0.y); t2[1] = __floats2half2_rn(t0.z, t0.w);
    t2[2] = __floats2half2_rn(t1.x, t1.y); t2[3] = __floats2half2_rn(t1.z, t1.w);

    const __half2 slope2 = __floats2half2_rn(SLOPE, SLOPE);

    float f[8];
    #pragma unroll
    for (int i = 0; i < 8; i++) f[i] = 0.f;
    float dw = 0.f;

    int start = off[n], cnt = deg[n];
    for (int base = 0; base < cnt; base += 32) {
        int rem = cnt - base;
        int m = rem < 32 ? rem : 32;
        int eld = (lane < m) ? __ldg(&eidx[start + base + lane]) : 0;
        int hm = (m + 1) >> 1;
        for (int j = 0; j < hm; j++) {
            int idx = 2 * j + sub;
            int s = __shfl_sync(0xffffffffu, eld, idx);
            uint4 araw = __ldg(&glh[(size_t)s * 16 + ll]);
            __half2 a2[4];
            a2[0] = *(__half2*)&araw.x; a2[1] = *(__half2*)&araw.y;
            a2[2] = *(__half2*)&araw.z; a2[3] = *(__half2*)&araw.w;

            __half2 acc = __floats2half2_rn(0.f, 0.f);
            #pragma unroll
            for (int i = 0; i < 4; i++) {
                __half2 s2 = __hadd2(a2[i], b2[i]);
                __half2 e2 = __hmax2(s2, __hmul2(s2, slope2));
                acc = __hfma2(e2, t2[i], acc);
            }
            float2 pf = __half22float2(acc);
            float p = pf.x + pf.y;
            p += __shfl_xor_sync(0xffffffffu, p, 2);
            p += __shfl_xor_sync(0xffffffffu, p, 1);
            float w = (idx < m) ? __expf(p) : 0.f;

            #pragma unroll
            for (int i = 0; i < 4; i++) {
                float2 af = __half22float2(a2[i]);
                f[2 * i]     += w * af.x;
                f[2 * i + 1] += w * af.y;
            }
            dw += w;
        }
    }

    #pragma unroll
    for (int i = 0; i < 8; i++) f[i] += __shfl_xor_sync(0xffffffffu, f[i], 16);
    dw += __shfl_xor_sync(0xffffffffu, dw, 16);

    if (sub == 0) {
        float inv = 1.0f / (dw + 1e-16f);
        uint32_t o[8];
        #pragma unroll
        for (int i = 0; i < 8; i++) {
            float v = f[i] * inv;
            if (mode == 1) v = v > 0.f ? v : expm1f(v);
            else           v = fmaxf(v, 0.f);
            o[i] = packsplit(v);
        }
        houtp[(size_t)n * 32 + 2 * ll]     = make_uint4(o[0], o[1], o[2], o[3]);
        houtp[(size_t)n * 32 + 2 * ll + 1] = make_uint4(o[4], o[5], o[6], o[7]);
    }
}

// ================= node layer 3 + log_softmax (H=1, F=40, fp32) =============
__global__ __launch_bounds__(256) void k_node_h1_lsm(
    const float4* __restrict__ gl4, const float4* __restrict__ gr4,
    const float* __restrict__ att,
    const int* __restrict__ off, const int* __restrict__ deg,
    const int* __restrict__ eidx, float* __restrict__ out)
{
    int n = blockIdx.x * 8 + (threadIdx.x >> 5);
    if (n >= N_NODES) return;
    int lane = threadIdx.x & 31;
    int sub = lane >> 4;
    int ll = lane & 15;

    float4 b = make_float4(0.f, 0.f, 0.f, 0.f), t = b;
    if (ll < 10) {
        b = gr4[(size_t)n * 10 + ll];
        t = __ldg(&((const float4*)att)[ll]);
    }

    float ax = 0.f, ay = 0.f, az = 0.f, aw = 0.f, dw = 0.f;

    int start = off[n], cnt = deg[n];
    for (int base = 0; base < cnt; base += 32) {
        int rem = cnt - base;
        int m = rem < 32 ? rem : 32;
        int eld = (lane < m) ? __ldg(&eidx[start + base + lane]) : 0;
        int hm = (m + 1) >> 1;
        for (int j = 0; j < hm; j++) {
            int idx = 2 * j + sub;
            int s = __shfl_sync(0xffffffffu, eld, idx);
            float4 a = make_float4(0.f, 0.f, 0.f, 0.f);
            float p = 0.f;
            if (ll < 10) {
                a = __ldg(&gl4[(size_t)s * 10 + ll]);
                float vx = a.x + b.x; vx = vx > 0.f ? vx : SLOPE * vx;
                float vy = a.y + b.y; vy = vy > 0.f ? vy : SLOPE * vy;
                float vz = a.z + b.z; vz = vz > 0.f ? vz : SLOPE * vz;
                float vw = a.w + b.w; vw = vw > 0.f ? vw : SLOPE * vw;
                p = vx * t.x + vy * t.y + vz * t.z + vw * t.w;
            }
            p += __shfl_xor_sync(0xffffffffu, p, 8, 16);
            p += __shfl_xor_sync(0xffffffffu, p, 4, 16);
            p += __shfl_xor_sync(0xffffffffu, p, 2, 16);
            p += __shfl_xor_sync(0xffffffffu, p, 1, 16);
            float w = (idx < m) ? __expf(p) : 0.f;
            ax += w * a.x; ay += w * a.y; az += w * a.z; aw += w * a.w;
            dw += w;
        }
    }

    ax += __shfl_xor_sync(0xffffffffu, ax, 16);
    ay += __shfl_xor_sync(0xffffffffu, ay, 16);
    az += __shfl_xor_sync(0xffffffffu, az, 16);
    aw += __shfl_xor_sync(0xffffffffu, aw, 16);
    dw += __shfl_xor_sync(0xffffffffu, dw, 16);

    float inv = 1.0f / (dw + 1e-16f);
    float4 v = make_float4(ax * inv, ay * inv, az * inv, aw * inv);

    float mx = (ll < 10) ? fmaxf(fmaxf(v.x, v.y), fmaxf(v.z, v.w)) : -FLT_MAX;
    #pragma unroll
    for (int o = 8; o > 0; o >>= 1) mx = fmaxf(mx, __shfl_xor_sync(0xffffffffu, mx, o, 16));
    float ss = (ll < 10)
        ? (expf(v.x - mx) + expf(v.y - mx) + expf(v.z - mx) + expf(v.w - mx)) : 0.f;
    #pragma unroll
    for (int o = 8; o > 0; o >>= 1) ss += __shfl_xor_sync(0xffffffffu, ss, o, 16);
    float lse = mx + logf(ss);
    if (sub == 0 && ll < 10) {
        float4 r = make_float4(v.x - lse, v.y - lse, v.z - lse, v.w - lse);
        *(float4*)(out + (size_t)n * 40 + 4 * ll) = r;
    }
}

// ---------------- host -------------------------------------------------------
extern "C" void kernel_launch(void* const* d_in, const int* in_sizes, int n_in,
                              void* d_out, int out_size)
{
    const float* x    = (const float*)d_in[0];
    const float* Wl1  = (const float*)d_in[1];
    const float* Wr1  = (const float*)d_in[2];
    const float* att1 = (const float*)d_in[3];
    const float* Wl2  = (const float*)d_in[4];
    const float* Wr2  = (const float*)d_in[5];
    const float* att2 = (const float*)d_in[6];
    const float* Wl3  = (const float*)d_in[7];
    const float* Wr3  = (const float*)d_in[8];
    const float* att3 = (const float*)d_in[9];
    const int*   ei   = (const int*)d_in[10];
    const int* src = ei;
    const int* dst = ei + N_EDGES;
    float* out = (float*)d_out;

    float *gl, *gr;
    uint32_t *hs, *ws, *w3s;
    int *deg, *off, *cur, *bsum, *eidx;
    cudaGetSymbolAddress((void**)&gl,   g_gl);
    cudaGetSymbolAddress((void**)&gr,   g_gr);
    cudaGetSymbolAddress((void**)&hs,   g_hs);
    cudaGetSymbolAddress((void**)&ws,   g_ws);
    cudaGetSymbolAddress((void**)&w3s,  g_w3s);
    cudaGetSymbolAddress((void**)&deg,  g_deg);
    cudaGetSymbolAddress((void**)&off,  g_off);
    cudaGetSymbolAddress((void**)&cur,  g_cur);
    cudaGetSymbolAddress((void**)&bsum, g_bsum);
    cudaGetSymbolAddress((void**)&eidx, g_eidx);

    __half* glh = (__half*)gl;
    __half* grh = (__half*)gr;

    const int GB = (N_NODES + 63) / 64;
    const int NB = (N_NODES + 7) / 8;
    const int NSCAN = (N_NODES + 1023) / 1024;
    const int EB4 = (N_EDGES / 4 + 255) / 256;   // 4 edges per thread

    static cudaStream_t s2 = nullptr;
    static cudaEvent_t evFork = nullptr, evJoin = nullptr;
    if (!s2) {
        cudaStreamCreateWithFlags(&s2, cudaStreamNonBlocking);
        cudaEventCreateWithFlags(&evFork, cudaEventDisableTiming);
        cudaEventCreateWithFlags(&evJoin, cudaEventDisableTiming);
    }

    // ---- fork: CSR build on s2, concurrent with weight split + layer-1 GEMM
    cudaEventRecord(evFork, 0);
    cudaStreamWaitEvent(s2, evFork, 0);
    cudaMemsetAsync(deg, 0, N_NODES * sizeof(int), s2);
    k_hist<<<EB4, 256, 0, s2>>>((const int4*)dst, deg);
    k_scan_part<<<NSCAN, 1024, 0, s2>>>(deg, off, bsum);
    k_scan_add<<<(N_NODES + 255) / 256, 256, 0, s2>>>(off, cur, bsum);
    k_scatter<<<EB4, 256, 0, s2>>>((const int4*)src, (const int4*)dst, cur, eidx);
    cudaEventRecord(evJoin, s2);

    // main stream: weight splits + layer-1 GEMM (reads raw fp32 x directly)
    k_split_w<<<80, 256>>>(Wl1, Wr1, Wl2, Wr2, ws, Wl3, Wr3, w3s);
    k_gemm_tc2<true><<<GB, 256>>>(nullptr, x, ws + 0 * 16384, ws + 1 * 16384,
                                  glh, grh, N_NODES);
    cudaStreamWaitEvent(0, evJoin, 0);

    // ---- Layer 1 aggregate ----
    k_node_h4<<<NB, 256>>>((const uint4*)glh, (const uint4*)grh, att1,
                           off, deg, eidx, (uint4*)hs, 1);
    // ---- Layer 2 ----
    k_gemm_tc2<false><<<GB, 256>>>(hs, nullptr, ws + 2 * 16384, ws + 3 * 16384,
                                   glh, grh, N_NODES);
    k_node_h4<<<NB, 256>>>((const uint4*)glh, (const uint4*)grh, att2,
                           off, deg, eidx, (uint4*)hs, 2);
    // ---- Layer 3 (TC GEMM, fp32 out; fused aggregate + log_softmax) ----
    k_gemm_tc3<<<GB, 256>>>(hs, w3s, gl, gr, N_NODES);
    k_node_h1_lsm<<<NB, 256>>>((const float4*)gl, (const float4*)gr, att3,
                               off, deg, eidx, out);
}

// round 15
// speedup vs baseline: 1.0078x; 1.0078x over previous
#include <cuda_runtime.h>
#include <cuda_bf16.h>
#include <cuda_fp16.h>
#include <math.h>
#include <float.h>
#include <stdint.h>

#define N_NODES 50000
#define N_EDGES 800000
#define SLOPE 0.2f

#if defined(__CUDA_ARCH__) && (__CUDA_ARCH__ >= 900)
#define GRID_DEP_SYNC() cudaGridDependencySynchronize()
#else
#define GRID_DEP_SYNC()
#endif

// ---------------- scratch (device globals; no allocation allowed) ----------
__device__ float    g_gl[N_NODES * 128];   // fp16 view (layers 1-2) / fp32 [N,40] (layer 3)
__device__ float    g_gr[N_NODES * 128];
__device__ uint32_t g_hs[N_NODES * 128];   // packed split of hidden h
__device__ uint32_t g_ws[4 * 16384];       // packed splits of Wl1,Wr1,Wl2,Wr2
__device__ uint32_t g_w3s[2 * 8192];       // packed splits of Wl3,Wr3 padded [128,64]
__device__ int      g_deg[N_NODES];
__device__ int      g_off[N_NODES];
__device__ int      g_cur[N_NODES];
__device__ int      g_bsum[64];
__device__ int      g_eidx[N_EDGES];

// ---- bf16 hi/lo split pack -------------------------------------------------
__device__ __forceinline__ uint32_t packsplit(float x) {
    __nv_bfloat16 h = __float2bfloat16(x);
    __nv_bfloat16 l = __float2bfloat16(x - __bfloat162float(h));
    return ((uint32_t)__bfloat16_as_ushort(h) << 16) | (uint32_t)__bfloat16_as_ushort(l);
}

// fused split: blocks 0-63 pack Wl1,Wr1,Wl2,Wr2 into g_ws;
// blocks 64-79 pack Wl3,Wr3 (40 cols, zero-padded to 64) into g_w3s.
__global__ void k_split_w(const float* __restrict__ w0, const float* __restrict__ w1,
                          const float* __restrict__ w2, const float* __restrict__ w3,
                          uint32_t* __restrict__ outp,
                          const float* __restrict__ w3a, const float* __restrict__ w3b,
                          uint32_t* __restrict__ out3) {
    if (blockIdx.x < 64) {
        int i = (blockIdx.x * 256 + threadIdx.x) * 4;
        int sel = i >> 14;
        int o4 = i & 16383;
        const float* w = (sel == 0) ? w0 : (sel == 1) ? w1 : (sel == 2) ? w2 : w3;
        float4 v = *(const float4*)(w + o4);
        uint4 o;
        o.x = packsplit(v.x); o.y = packsplit(v.y);
        o.z = packsplit(v.z); o.w = packsplit(v.w);
        *(uint4*)(outp + i) = o;
    } else {
        int g = (blockIdx.x - 64) * 256 + threadIdx.x;   // 0..4095
        int sel = g >> 11;
        int gg = g & 2047;
        int e0 = gg * 4;
        int k = e0 >> 6, c = e0 & 63;
        const float* w = sel ? w3b : w3a;
        uint32_t o[4];
        #pragma unroll
        for (int j = 0; j < 4; j++) {
            float v = (c + j < 40) ? w[k * 40 + c + j] : 0.f;
            o[j] = packsplit(v);
        }
        *(uint4*)(out3 + sel * 8192 + k * 64 + c) = make_uint4(o[0], o[1], o[2], o[3]);
    }
}

// ================= CSR construction ==========================================
__global__ void k_hist(const int* __restrict__ dst, int* __restrict__ deg) {
    int e = blockIdx.x * blockDim.x + threadIdx.x;
    if (e < N_EDGES) atomicAdd(&deg[dst[e]], 1);
}

__global__ __launch_bounds__(1024) void k_scan_part(
    const int* __restrict__ deg, int* __restrict__ off, int* __restrict__ bsum)
{
    __shared__ int sh[1024];
    int t = threadIdx.x;
    int i = blockIdx.x * 1024 + t;
    int v = (i < N_NODES) ? deg[i] : 0;
    sh[t] = v;
    __syncthreads();
    #pragma unroll
    for (int o = 1; o < 1024; o <<= 1) {
        int u = (t >= o) ? sh[t - o] : 0;
        __syncthreads();
        sh[t] += u;
        __syncthreads();
    }
    if (i < N_NODES) off[i] = sh[t] - v;
    if (t == 1023) bsum[blockIdx.x] = sh[t];
}

__global__ void k_scan_add(int* __restrict__ off, int* __restrict__ cur,
                           const int* __restrict__ bsum)
{
    __shared__ int base_sh;
    int i = blockIdx.x * blockDim.x + threadIdx.x;
    int b = (blockIdx.x * blockDim.x) >> 10;
    if (threadIdx.x == 0) {
        int s = 0;
        for (int j = 0; j < b; j++) s += bsum[j];
        base_sh = s;
    }
    __syncthreads();
    if (i >= N_NODES) return;
    int o = off[i] + base_sh;
    off[i] = o;
    cur[i] = o;
}

__global__ void k_scatter(const int* __restrict__ src, const int* __restrict__ dst,
                          int* __restrict__ cur, int* __restrict__ eidx)
{
    int e = blockIdx.x * blockDim.x + threadIdx.x;
    if (e >= N_EDGES) return;
    int p = atomicAdd(&cur[dst[e]], 1);
    eidx[p] = src[e];
}

// ================= tensor-core helpers =======================================
__device__ __forceinline__ uint32_t smem_u32(const void* p) {
    return (uint32_t)__cvta_generic_to_shared(p);
}
__device__ __forceinline__ void ldsm_x4(uint32_t& r0, uint32_t& r1, uint32_t& r2, uint32_t& r3, uint32_t addr) {
    asm volatile("ldmatrix.sync.aligned.m8n8.x4.shared.b16 {%0,%1,%2,%3},[%4];"
                 : "=r"(r0), "=r"(r1), "=r"(r2), "=r"(r3) : "r"(addr));
}
__device__ __forceinline__ void ldsm_x2_t(uint32_t& r0, uint32_t& r1, uint32_t addr) {
    asm volatile("ldmatrix.sync.aligned.m8n8.x2.trans.shared.b16 {%0,%1},[%2];"
                 : "=r"(r0), "=r"(r1) : "r"(addr));
}
__device__ __forceinline__ void mma_bf16c(float* d, const uint32_t* a, const uint32_t* b) {
    asm volatile("mma.sync.aligned.m16n8k16.row.col.f32.bf16.bf16.f32 "
                 "{%0,%1,%2,%3},{%4,%5,%6,%7},{%8,%9},{%0,%1,%2,%3};"
                 : "+f"(d[0]), "+f"(d[1]), "+f"(d[2]), "+f"(d[3])
                 : "r"(a[0]), "r"(a[1]), "r"(a[2]), "r"(a[3]), "r"(b[0]), "r"(b[1]));
}

// ================= TC dual GEMM (layers 1-2), fp16 output ===================
// 2-product error-compensated: ah*wh + al*wh.
// PDL: RAW=true loads A (ready input x) first, gridsync before W (pending
// split). RAW=false loads W (ready) first, gridsync before A (pending hs).
template <bool RAW>
__global__ __launch_bounds__(256, 2) void k_gemm_tc2(
    const uint32_t* __restrict__ Ap, const float* __restrict__ Araw,
    const uint32_t* __restrict__ W1p, const uint32_t* __restrict__ W2p,
    __half* __restrict__ C1, __half* __restrict__ C2, int M)
{
    __shared__ __nv_bfloat16 Ah[64][40];
    __shared__ __nv_bfloat16 Al[64][40];
    __shared__ __nv_bfloat16 Wh[32][264];

    const int tid = threadIdx.x, lane = tid & 31, wid = tid >> 5;
    const int wm = wid & 1;
    const int wn = wid >> 1;
    const int r0 = blockIdx.x * 64;

    float d[2][8][4];
    #pragma unroll
    for (int i = 0; i < 2; i++)
        #pragma unroll
        for (int j = 0; j < 8; j++)
            #pragma unroll
            for (int k = 0; k < 4; k++) d[i][j][k] = 0.f;

    for (int kt = 0; kt < 4; kt++) {
        if (RAW) {
            // A first (input x is launch-ready)
            #pragma unroll
            for (int i = 0; i < 2; i++) {
                int idx = tid + i * 256;
                int row = idx >> 3, q = idx & 7;
                float4 v = make_float4(0.f, 0.f, 0.f, 0.f);
                if (r0 + row < M)
                    v = *(const float4*)(Araw + (size_t)(r0 + row) * 128 + kt * 32 + q * 4);
                float ar[4] = {v.x, v.y, v.z, v.w};
                __nv_bfloat16 h[4], lo[4];
                #pragma unroll
                for (int j = 0; j < 4; j++) {
                    h[j] = __float2bfloat16(ar[j]);
                    lo[j] = __float2bfloat16(ar[j] - __bfloat162float(h[j]));
                }
                *(uint2*)&Ah[row][q * 4] = *(uint2*)h;
                *(uint2*)&Al[row][q * 4] = *(uint2*)lo;
            }
            if (kt == 0) GRID_DEP_SYNC();
            #pragma unroll
            for (int i = 0; i < 8; i++) {
                int idx = tid + i * 256;
                int k = idx >> 6, q = idx & 63;
                uint4 p = (q < 32)
                    ? *(const uint4*)(W1p + (size_t)(kt * 32 + k) * 128 + q * 4)
                    : *(const uint4*)(W2p + (size_t)(kt * 32 + k) * 128 + (q - 32) * 4);
                uint2 hi;
                hi.x = __byte_perm(p.x, p.y, 0x7632); hi.y = __byte_perm(p.z, p.w, 0x7632);
                *(uint2*)&Wh[k][q * 4] = hi;
            }
        } else {
            // W first (weights split long before)
            #pragma unroll
            for (int i = 0; i < 8; i++) {
                int idx = tid + i * 256;
                int k = idx >> 6, q = idx & 63;
                uint4 p = (q < 32)
                    ? *(const uint4*)(W1p + (size_t)(kt * 32 + k) * 128 + q * 4)
                    : *(const uint4*)(W2p + (size_t)(kt * 32 + k) * 128 + (q - 32) * 4);
                uint2 hi;
                hi.x = __byte_perm(p.x, p.y, 0x7632); hi.y = __byte_perm(p.z, p.w, 0x7632);
                *(uint2*)&Wh[k][q * 4] = hi;
            }
            if (kt == 0) GRID_DEP_SYNC();
            #pragma unroll
            for (int i = 0; i < 2; i++) {
                int idx = tid + i * 256;
                int row = idx >> 3, q = idx & 7;
                uint4 p = make_uint4(0u, 0u, 0u, 0u);
                if (r0 + row < M)
                    p = *(const uint4*)(Ap + (size_t)(r0 + row) * 128 + kt * 32 + q * 4);
                uint2 hi, lo;
                hi.x = __byte_perm(p.x, p.y, 0x7632); hi.y = __byte_perm(p.z, p.w, 0x7632);
                lo.x = __byte_perm(p.x, p.y, 0x5410); lo.y = __byte_perm(p.z, p.w, 0x5410);
                *(uint2*)&Ah[row][q * 4] = hi;
                *(uint2*)&Al[row][q * 4] = lo;
            }
        }
        __syncthreads();

        #pragma unroll
        for (int ph = 0; ph < 2; ph++) {
            const __nv_bfloat16 (*Asm)[40] = (ph == 1) ? Al : Ah;
            #pragma unroll
            for (int k16 = 0; k16 < 2; k16++) {
                uint32_t af[2][4], bfr[8][2];
                #pragma unroll
                for (int mf = 0; mf < 2; mf++) {
                    uint32_t addr = smem_u32(
                        &Asm[wm * 32 + mf * 16 + (lane & 15)][k16 * 16 + (lane >> 4) * 8]);
                    ldsm_x4(af[mf][0], af[mf][1], af[mf][2], af[mf][3], addr);
                }
                #pragma unroll
                for (int nf = 0; nf < 8; nf++) {
                    uint32_t addr = smem_u32(
                        &Wh[k16 * 16 + (lane & 15)][wn * 64 + nf * 8]);
                    ldsm_x2_t(bfr[nf][0], bfr[nf][1], addr);
                }
                #pragma unroll
                for (int mf = 0; mf < 2; mf++)
                    #pragma unroll
                    for (int nf = 0; nf < 8; nf++)
                        mma_bf16c(d[mf][nf], af[mf], bfr[nf]);
            }
        }
        __syncthreads();
    }

    const int g = lane >> 2, t = lane & 3;
    __half* Cp = (wn < 2) ? C1 : C2;
    int cbase = (wn < 2) ? wn * 64 : (wn - 2) * 64;
    #pragma unroll
    for (int mf = 0; mf < 2; mf++) {
        #pragma unroll
        for (int nf = 0; nf < 8; nf++) {
            int row0 = r0 + wm * 32 + mf * 16 + g;
            int col = cbase + nf * 8 + t * 2;
            if (row0 < M)
                *(__half2*)(Cp + (size_t)row0 * 128 + col) =
                    __floats2half2_rn(d[mf][nf][0], d[mf][nf][1]);
            if (row0 + 8 < M)
                *(__half2*)(Cp + (size_t)(row0 + 8) * 128 + col) =
                    __floats2half2_rn(d[mf][nf][2], d[mf][nf][3]);
        }
    }
}

// ================= TC dual GEMM layer 3 (N=40 padded to 64, fp32 out) =======
__global__ __launch_bounds__(256, 2) void k_gemm_tc3(
    const uint32_t* __restrict__ Ap, const uint32_t* __restrict__ W3p,
    float* __restrict__ C1, float* __restrict__ C2, int M)
{
    __shared__ __nv_bfloat16 Ah[64][40];
    __shared__ __nv_bfloat16 Al[64][40];
    __shared__ __nv_bfloat16 Wh[32][136];

    const int tid = threadIdx.x, lane = tid & 31, wid = tid >> 5;
    const int wm = wid & 1;
    const int wn = wid >> 1;
    const int r0 = blockIdx.x * 64;

    float d[2][4][4];
    #pragma unroll
    for (int i = 0; i < 2; i++)
        #pragma unroll
        for (int j = 0; j < 4; j++)
            #pragma unroll
            for (int k = 0; k < 4; k++) d[i][j][k] = 0.f;

    for (int kt = 0; kt < 4; kt++) {
        // W first (ready), gridsync, then A (pending hs)
        #pragma unroll
        for (int i = 0; i < 4; i++) {
            int idx = tid + i * 256;
            int k = idx >> 5, q = idx & 31;
            const uint32_t* src = W3p + ((q >= 16) ? 8192 : 0)
                                + (size_t)(kt * 32 + k) * 64 + (q & 15) * 4;
            uint4 p = *(const uint4*)src;
            uint2 hi;
            hi.x = __byte_perm(p.x, p.y, 0x7632); hi.y = __byte_perm(p.z, p.w, 0x7632);
            *(uint2*)&Wh[k][q * 4] = hi;
        }
        if (kt == 0) GRID_DEP_SYNC();
        #pragma unroll
        for (int i = 0; i < 2; i++) {
            int idx = tid + i * 256;
            int row = idx >> 3, q = idx & 7;
            uint4 p = make_uint4(0u, 0u, 0u, 0u);
            if (r0 + row < M)
                p = *(const uint4*)(Ap + (size_t)(r0 + row) * 128 + kt * 32 + q * 4);
            uint2 hi, lo;
            hi.x = __byte_perm(p.x, p.y, 0x7632); hi.y = __byte_perm(p.z, p.w, 0x7632);
            lo.x = __byte_perm(p.x, p.y, 0x5410); lo.y = __byte_perm(p.z, p.w, 0x5410);
            *(uint2*)&Ah[row][q * 4] = hi;
            *(uint2*)&Al[row][q * 4] = lo;
        }
        __syncthreads();

        #pragma unroll
        for (int ph = 0; ph < 2; ph++) {
            const __nv_bfloat16 (*Asm)[40] = (ph == 1) ? Al : Ah;
            #pragma unroll
            for (int k16 = 0; k16 < 2; k16++) {
                uint32_t af[2][4], bfr[4][2];
                #pragma unroll
                for (int mf = 0; mf < 2; mf++) {
                    uint32_t addr = smem_u32(
                        &Asm[wm * 32 + mf * 16 + (lane & 15)][k16 * 16 + (lane >> 4) * 8]);
                    ldsm_x4(af[mf][0], af[mf][1], af[mf][2], af[mf][3], addr);
                }
                #pragma unroll
                for (int nf = 0; nf < 4; nf++) {
                    uint32_t addr = smem_u32(
                        &Wh[k16 * 16 + (lane & 15)][wn * 32 + nf * 8]);
                    ldsm_x2_t(bfr[nf][0], bfr[nf][1], addr);
                }
                #pragma unroll
                for (int mf = 0; mf < 2; mf++)
                    #pragma unroll
                    for (int nf = 0; nf < 4; nf++)
                        mma_bf16c(d[mf][nf], af[mf], bfr[nf]);
            }
        }
        __syncthreads();
    }

    const int g = lane >> 2, t = lane & 3;
    float* Cp = (wn < 2) ? C1 : C2;
    int cbase = (wn & 1) * 32;
    #pragma unroll
    for (int mf = 0; mf < 2; mf++) {
        #pragma unroll
        for (int nf = 0; nf < 4; nf++) {
            int row0 = r0 + wm * 32 + mf * 16 + g;
            int col = cbase + nf * 8 + t * 2;
            if (col >= 40) continue;
            if (row0 < M)
                *(float2*)(Cp + (size_t)row0 * 40 + col) = make_float2(d[mf][nf][0], d[mf][nf][1]);
            if (row0 + 8 < M)
                *(float2*)(Cp + (size_t)(row0 + 8) * 40 + col) = make_float2(d[mf][nf][2], d[mf][nf][3]);
        }
    }
}

// ================= node aggregation (H=4, F=32), half2 math, 2 edges/warp ===
__global__ __launch_bounds__(256) void k_node_h4(
    const uint4* __restrict__ glh, const uint4* __restrict__ grh,
    const float* __restrict__ att,
    const int* __restrict__ off, const int* __restrict__ deg,
    const int* __restrict__ eidx, uint4* __restrict__ houtp, int mode)
{
    int n = blockIdx.x * 8 + (threadIdx.x >> 5);
    if (n >= N_NODES) return;
    int lane = threadIdx.x & 31;
    int sub = lane >> 4;
    int ll = lane & 15;

    // att is a launch-ready input — load before the dependency sync
    float4 t0 = __ldg((const float4*)att + 2 * ll);
    float4 t1 = __ldg((const float4*)att + 2 * ll + 1);
    __half2 t2[4];
    t2[0] = __floats2half2_rn(t0.x, t0.y); t2[1] = __floats2half2_rn(t0.z, t0.w);
    t2[2] = __floats2half2_rn(t1.x, t1.y); t2[3] = __floats2half2_rn(t1.z, t1.w);
    const __half2 slope2 = __floats2half2_rn(SLOPE, SLOPE);

    GRID_DEP_SYNC();

    uint4 braw = grh[(size_t)n * 16 + ll];
    __half2 b2[4];
    b2[0] = *(__half2*)&braw.x; b2[1] = *(__half2*)&braw.y;
    b2[2] = *(__half2*)&braw.z; b2[3] = *(__half2*)&braw.w;

    float f[8];
    #pragma unroll
    for (int i = 0; i < 8; i++) f[i] = 0.f;
    float dw = 0.f;

    int start = off[n], cnt = deg[n];
    for (int base = 0; base < cnt; base += 32) {
        int rem = cnt - base;
        int m = rem < 32 ? rem : 32;
        int eld = (lane < m) ? __ldg(&eidx[start + base + lane]) : 0;
        int hm = (m + 1) >> 1;
        for (int j = 0; j < hm; j++) {
            int idx = 2 * j + sub;
            int s = __shfl_sync(0xffffffffu, eld, idx);
            uint4 araw = __ldg(&glh[(size_t)s * 16 + ll]);
            __half2 a2[4];
            a2[0] = *(__half2*)&araw.x; a2[1] = *(__half2*)&araw.y;
            a2[2] = *(__half2*)&araw.z; a2[3] = *(__half2*)&araw.w;

            __half2 acc = __floats2half2_rn(0.f, 0.f);
            #pragma unroll
            for (int i = 0; i < 4; i++) {
                __half2 s2 = __hadd2(a2[i], b2[i]);
                __half2 e2 = __hmax2(s2, __hmul2(s2, slope2));
                acc = __hfma2(e2, t2[i], acc);
            }
            float2 pf = __half22float2(acc);
            float p = pf.x + pf.y;
            p += __shfl_xor_sync(0xffffffffu, p, 2);
            p += __shfl_xor_sync(0xffffffffu, p, 1);
            float w = (idx < m) ? __expf(p) : 0.f;

            #pragma unroll
            for (int i = 0; i < 4; i++) {
                float2 af = __half22float2(a2[i]);
                f[2 * i]     += w * af.x;
                f[2 * i + 1] += w * af.y;
            }
            dw += w;
        }
    }

    #pragma unroll
    for (int i = 0; i < 8; i++) f[i] += __shfl_xor_sync(0xffffffffu, f[i], 16);
    dw += __shfl_xor_sync(0xffffffffu, dw, 16);

    if (sub == 0) {
        float inv = 1.0f / (dw + 1e-16f);
        uint32_t o[8];
        #pragma unroll
        for (int i = 0; i < 8; i++) {
            float v = f[i] * inv;
            if (mode == 1) v = v > 0.f ? v : expm1f(v);
            else           v = fmaxf(v, 0.f);
            o[i] = packsplit(v);
        }
        houtp[(size_t)n * 32 + 2 * ll]     = make_uint4(o[0], o[1], o[2], o[3]);
        houtp[(size_t)n * 32 + 2 * ll + 1] = make_uint4(o[4], o[5], o[6], o[7]);
    }
}

// ================= node layer 3 + log_softmax (H=1, F=40, fp32) =============
__global__ __launch_bounds__(256) void k_node_h1_lsm(
    const float4* __restrict__ gl4, const float4* __restrict__ gr4,
    const float* __restrict__ att,
    const int* __restrict__ off, const int* __restrict__ deg,
    const int* __restrict__ eidx, float* __restrict__ out)
{
    int n = blockIdx.x * 8 + (threadIdx.x >> 5);
    if (n >= N_NODES) return;
    int lane = threadIdx.x & 31;
    int sub = lane >> 4;
    int ll = lane & 15;

    float4 t = make_float4(0.f, 0.f, 0.f, 0.f);
    if (ll < 10) t = __ldg(&((const float4*)att)[ll]);

    GRID_DEP_SYNC();

    float4 b = make_float4(0.f, 0.f, 0.f, 0.f);
    if (ll < 10) b = gr4[(size_t)n * 10 + ll];

    float ax = 0.f, ay = 0.f, az = 0.f, aw = 0.f, dw = 0.f;

    int start = off[n], cnt = deg[n];
    for (int base = 0; base < cnt; base += 32) {
        int rem = cnt - base;
        int m = rem < 32 ? rem : 32;
        int eld = (lane < m) ? __ldg(&eidx[start + base + lane]) : 0;
        int hm = (m + 1) >> 1;
        for (int j = 0; j < hm; j++) {
            int idx = 2 * j + sub;
            int s = __shfl_sync(0xffffffffu, eld, idx);
            float4 a = make_float4(0.f, 0.f, 0.f, 0.f);
            float p = 0.f;
            if (ll < 10) {
                a = __ldg(&gl4[(size_t)s * 10 + ll]);
                float vx = a.x + b.x; vx = vx > 0.f ? vx : SLOPE * vx;
                float vy = a.y + b.y; vy = vy > 0.f ? vy : SLOPE * vy;
                float vz = a.z + b.z; vz = vz > 0.f ? vz : SLOPE * vz;
                float vw = a.w + b.w; vw = vw > 0.f ? vw : SLOPE * vw;
                p = vx * t.x + vy * t.y + vz * t.z + vw * t.w;
            }
            p += __shfl_xor_sync(0xffffffffu, p, 8, 16);
            p += __shfl_xor_sync(0xffffffffu, p, 4, 16);
            p += __shfl_xor_sync(0xffffffffu, p, 2, 16);
            p += __shfl_xor_sync(0xffffffffu, p, 1, 16);
            float w = (idx < m) ? __expf(p) : 0.f;
            ax += w * a.x; ay += w * a.y; az += w * a.z; aw += w * a.w;
            dw += w;
        }
    }

    ax += __shfl_xor_sync(0xffffffffu, ax, 16);
    ay += __shfl_xor_sync(0xffffffffu, ay, 16);
    az += __shfl_xor_sync(0xffffffffu, az, 16);
    aw += __shfl_xor_sync(0xffffffffu, aw, 16);
    dw += __shfl_xor_sync(0xffffffffu, dw, 16);

    float inv = 1.0f / (dw + 1e-16f);
    float4 v = make_float4(ax * inv, ay * inv, az * inv, aw * inv);

    float mx = (ll < 10) ? fmaxf(fmaxf(v.x, v.y), fmaxf(v.z, v.w)) : -FLT_MAX;
    #pragma unroll
    for (int o = 8; o > 0; o >>= 1) mx = fmaxf(mx, __shfl_xor_sync(0xffffffffu, mx, o, 16));
    float ss = (ll < 10)
        ? (expf(v.x - mx) + expf(v.y - mx) + expf(v.z - mx) + expf(v.w - mx)) : 0.f;
    #pragma unroll
    for (int o = 8; o > 0; o >>= 1) ss += __shfl_xor_sync(0xffffffffu, ss, o, 16);
    float lse = mx + logf(ss);
    if (sub == 0 && ll < 10) {
        float4 r = make_float4(v.x - lse, v.y - lse, v.z - lse, v.w - lse);
        *(float4*)(out + (size_t)n * 40 + 4 * ll) = r;
    }
}

// ---------------- host -------------------------------------------------------
extern "C" void kernel_launch(void* const* d_in, const int* in_sizes, int n_in,
                              void* d_out, int out_size)
{
    const float* x    = (const float*)d_in[0];
    const float* Wl1  = (const float*)d_in[1];
    const float* Wr1  = (const float*)d_in[2];
    const float* att1 = (const float*)d_in[3];
    const float* Wl2  = (const float*)d_in[4];
    const float* Wr2  = (const float*)d_in[5];
    const float* att2 = (const float*)d_in[6];
    const float* Wl3  = (const float*)d_in[7];
    const float* Wr3  = (const float*)d_in[8];
    const float* att3 = (const float*)d_in[9];
    const int*   ei   = (const int*)d_in[10];
    const int* src = ei;
    const int* dst = ei + N_EDGES;
    float* out = (float*)d_out;

    float *gl, *gr;
    uint32_t *hs, *ws, *w3s;
    int *deg, *off, *cur, *bsum, *eidx;
    cudaGetSymbolAddress((void**)&gl,   g_gl);
    cudaGetSymbolAddress((void**)&gr,   g_gr);
    cudaGetSymbolAddress((void**)&hs,   g_hs);
    cudaGetSymbolAddress((void**)&ws,   g_ws);
    cudaGetSymbolAddress((void**)&w3s,  g_w3s);
    cudaGetSymbolAddress((void**)&deg,  g_deg);
    cudaGetSymbolAddress((void**)&off,  g_off);
    cudaGetSymbolAddress((void**)&cur,  g_cur);
    cudaGetSymbolAddress((void**)&bsum, g_bsum);
    cudaGetSymbolAddress((void**)&eidx, g_eidx);

    __half* glh = (__half*)gl;
    __half* grh = (__half*)gr;

    const int GB = (N_NODES + 63) / 64;
    const int NB = (N_NODES + 7) / 8;
    const int NSCAN = (N_NODES + 1023) / 1024;

    static cudaStream_t s2 = nullptr;
    static cudaEvent_t evFork = nullptr, evJoin = nullptr;
    if (!s2) {
        cudaStreamCreateWithFlags(&s2, cudaStreamNonBlocking);
        cudaEventCreateWithFlags(&evFork, cudaEventDisableTiming);
        cudaEventCreateWithFlags(&evJoin, cudaEventDisableTiming);
    }

    // PDL launch helper (main stream, programmatic serialization allowed)
    cudaLaunchAttribute pdlAttr;
    pdlAttr.id = cudaLaunchAttributeProgrammaticStreamSerialization;
    pdlAttr.val.programmaticStreamSerializationAllowed = 1;
    cudaLaunchConfig_t cfg = {};
    cfg.blockDim = {256, 1, 1};
    cfg.stream = 0;
    cfg.attrs = &pdlAttr;
    cfg.numAttrs = 1;

    // ---- fork: CSR build on s2, concurrent with weight split + layer-1 GEMM
    cudaEventRecord(evFork, 0);
    cudaStreamWaitEvent(s2, evFork, 0);
    cudaMemsetAsync(deg, 0, N_NODES * sizeof(int), s2);
    k_hist<<<(N_EDGES + 255) / 256, 256, 0, s2>>>(dst, deg);
    k_scan_part<<<NSCAN, 1024, 0, s2>>>(deg, off, bsum);
    k_scan_add<<<(N_NODES + 255) / 256, 256, 0, s2>>>(off, cur, bsum);
    k_scatter<<<(N_EDGES + 255) / 256, 256, 0, s2>>>(src, dst, cur, eidx);
    cudaEventRecord(evJoin, s2);

    // main stream: weight splits, then layer-1 GEMM (PDL: A=x ready, W pending)
    k_split_w<<<80, 256>>>(Wl1, Wr1, Wl2, Wr2, ws, Wl3, Wr3, w3s);
    {
        cfg.gridDim = {(unsigned)GB, 1, 1};
        const uint32_t* ap = nullptr;
        cudaLaunchKernelEx(&cfg, k_gemm_tc2<true>, ap, x,
                           (const uint32_t*)(ws + 0 * 16384),
                           (const uint32_t*)(ws + 1 * 16384),
                           glh, grh, (int)N_NODES);
    }
    cudaStreamWaitEvent(0, evJoin, 0);

    // ---- Layer 1 aggregate (PDL) ----
    {
        cfg.gridDim = {(unsigned)NB, 1, 1};
        cudaLaunchKernelEx(&cfg, k_node_h4,
                           (const uint4*)glh, (const uint4*)grh, att1,
                           (const int*)off, (const int*)deg, (const int*)eidx,
                           (uint4*)hs, 1);
    }
    // ---- Layer 2 ----
    {
        cfg.gridDim = {(unsigned)GB, 1, 1};
        const float* araw = nullptr;
        cudaLaunchKernelEx(&cfg, k_gemm_tc2<false>, (const uint32_t*)hs, araw,
                           (const uint32_t*)(ws + 2 * 16384),
                           (const uint32_t*)(ws + 3 * 16384),
                           glh, grh, (int)N_NODES);
    }
    {
        cfg.gridDim = {(unsigned)NB, 1, 1};
        cudaLaunchKernelEx(&cfg, k_node_h4,
                           (const uint4*)glh, (const uint4*)grh, att2,
                           (const int*)off, (const int*)deg, (const int*)eidx,
                           (uint4*)hs, 2);
    }
    // ---- Layer 3 (TC GEMM, fp32 out; fused aggregate + log_softmax) ----
    {
        cfg.gridDim = {(unsigned)GB, 1, 1};
        cudaLaunchKernelEx(&cfg, k_gemm_tc3, (const uint32_t*)hs,
                           (const uint32_t*)w3s, gl, gr, (int)N_NODES);
    }
    {
        cfg.gridDim = {(unsigned)NB, 1, 1};
        cudaLaunchKernelEx(&cfg, k_node_h1_lsm,
                           (const float4*)gl, (const float4*)gr, att3,
                           (const int*)off, (const int*)deg, (const int*)eidx,
                           out);
    }
}

// round 16
// speedup vs baseline: 1.1522x; 1.1433x over previous
#include <cuda_runtime.h>
#include <cuda_bf16.h>
#include <cuda_fp16.h>
#include <math.h>
#include <float.h>
#include <stdint.h>

#define N_NODES 50000
#define N_EDGES 800000
#define SLOPE 0.2f

#if defined(__CUDA_ARCH__) && (__CUDA_ARCH__ >= 900)
#define GRID_DEP_SYNC() cudaGridDependencySynchronize()
#else
#define GRID_DEP_SYNC()
#endif

// ---------------- scratch (device globals; no allocation allowed) ----------
__device__ float          g_gl[N_NODES * 128];  // fp16 view (layers 1-2) / fp32 [N,40] (layer 3)
__device__ float          g_gr[N_NODES * 128];
__device__ __nv_bfloat16  g_hsb[N_NODES * 128]; // bf16 hidden h
__device__ __nv_bfloat16  g_wsb[4 * 16384];     // bf16 Wl1,Wr1,Wl2,Wr2
__device__ __nv_bfloat16  g_w3sb[2 * 8192];     // bf16 Wl3,Wr3 padded [128,64]
__device__ int            g_deg[N_NODES];
__device__ int            g_off[N_NODES];
__device__ int            g_cur[N_NODES];
__device__ int            g_bsum[64];
__device__ int            g_eidx[N_EDGES];

// fused convert: blocks 0-63 cvt Wl1,Wr1,Wl2,Wr2 -> g_wsb;
// blocks 64-79 cvt Wl3,Wr3 (40 cols, zero-padded to 64) -> g_w3sb.
__global__ void k_split_w(const float* __restrict__ w0, const float* __restrict__ w1,
                          const float* __restrict__ w2, const float* __restrict__ w3,
                          __nv_bfloat16* __restrict__ outb,
                          const float* __restrict__ w3a, const float* __restrict__ w3b,
                          __nv_bfloat16* __restrict__ out3b) {
    if (blockIdx.x < 64) {
        int i = (blockIdx.x * 256 + threadIdx.x) * 4;
        int sel = i >> 14;
        int o4 = i & 16383;
        const float* w = (sel == 0) ? w0 : (sel == 1) ? w1 : (sel == 2) ? w2 : w3;
        float4 v = *(const float4*)(w + o4);
        __nv_bfloat16 ob[4];
        ob[0] = __float2bfloat16(v.x); ob[1] = __float2bfloat16(v.y);
        ob[2] = __float2bfloat16(v.z); ob[3] = __float2bfloat16(v.w);
        *(uint2*)(outb + i) = *(uint2*)ob;
    } else {
        int g = (blockIdx.x - 64) * 256 + threadIdx.x;   // 0..4095
        int sel = g >> 11;
        int gg = g & 2047;
        int e0 = gg * 4;
        int k = e0 >> 6, c = e0 & 63;
        const float* w = sel ? w3b : w3a;
        __nv_bfloat16 ob[4];
        #pragma unroll
        for (int j = 0; j < 4; j++) {
            float v = (c + j < 40) ? w[k * 40 + c + j] : 0.f;
            ob[j] = __float2bfloat16(v);
        }
        *(uint2*)(out3b + sel * 8192 + k * 64 + c) = *(uint2*)ob;
    }
}

// ================= CSR construction ==========================================
__global__ void k_hist(const int* __restrict__ dst, int* __restrict__ deg) {
    int e = blockIdx.x * blockDim.x + threadIdx.x;
    if (e < N_EDGES) atomicAdd(&deg[dst[e]], 1);
}

__global__ __launch_bounds__(1024) void k_scan_part(
    const int* __restrict__ deg, int* __restrict__ off, int* __restrict__ bsum)
{
    __shared__ int sh[1024];
    int t = threadIdx.x;
    int i = blockIdx.x * 1024 + t;
    int v = (i < N_NODES) ? deg[i] : 0;
    sh[t] = v;
    __syncthreads();
    #pragma unroll
    for (int o = 1; o < 1024; o <<= 1) {
        int u = (t >= o) ? sh[t - o] : 0;
        __syncthreads();
        sh[t] += u;
        __syncthreads();
    }
    if (i < N_NODES) off[i] = sh[t] - v;
    if (t == 1023) bsum[blockIdx.x] = sh[t];
}

__global__ void k_scan_add(int* __restrict__ off, int* __restrict__ cur,
                           const int* __restrict__ bsum)
{
    __shared__ int base_sh;
    int i = blockIdx.x * blockDim.x + threadIdx.x;
    int b = (blockIdx.x * blockDim.x) >> 10;
    if (threadIdx.x == 0) {
        int s = 0;
        for (int j = 0; j < b; j++) s += bsum[j];
        base_sh = s;
    }
    __syncthreads();
    if (i >= N_NODES) return;
    int o = off[i] + base_sh;
    off[i] = o;
    cur[i] = o;
}

__global__ void k_scatter(const int* __restrict__ src, const int* __restrict__ dst,
                          int* __restrict__ cur, int* __restrict__ eidx)
{
    int e = blockIdx.x * blockDim.x + threadIdx.x;
    if (e >= N_EDGES) return;
    int p = atomicAdd(&cur[dst[e]], 1);
    eidx[p] = src[e];
}

// ================= tensor-core helpers =======================================
__device__ __forceinline__ uint32_t smem_u32(const void* p) {
    return (uint32_t)__cvta_generic_to_shared(p);
}
__device__ __forceinline__ void ldsm_x4(uint32_t& r0, uint32_t& r1, uint32_t& r2, uint32_t& r3, uint32_t addr) {
    asm volatile("ldmatrix.sync.aligned.m8n8.x4.shared.b16 {%0,%1,%2,%3},[%4];"
                 : "=r"(r0), "=r"(r1), "=r"(r2), "=r"(r3) : "r"(addr));
}
__device__ __forceinline__ void ldsm_x2_t(uint32_t& r0, uint32_t& r1, uint32_t addr) {
    asm volatile("ldmatrix.sync.aligned.m8n8.x2.trans.shared.b16 {%0,%1},[%2];"
                 : "=r"(r0), "=r"(r1) : "r"(addr));
}
__device__ __forceinline__ void mma_bf16c(float* d, const uint32_t* a, const uint32_t* b) {
    asm volatile("mma.sync.aligned.m16n8k16.row.col.f32.bf16.bf16.f32 "
                 "{%0,%1,%2,%3},{%4,%5,%6,%7},{%8,%9},{%0,%1,%2,%3};"
                 : "+f"(d[0]), "+f"(d[1]), "+f"(d[2]), "+f"(d[3])
                 : "r"(a[0]), "r"(a[1]), "r"(a[2]), "r"(a[3]), "r"(b[0]), "r"(b[1]));
}

// ================= TC dual GEMM (layers 1-2), pure bf16, fp16 output ========
// RAW=true: A raw fp32 x, cvt in-register. RAW=false: A bf16 (hsb).
template <bool RAW>
__global__ __launch_bounds__(256, 2) void k_gemm_tc2(
    const __nv_bfloat16* __restrict__ Ab, const float* __restrict__ Araw,
    const __nv_bfloat16* __restrict__ W1b, const __nv_bfloat16* __restrict__ W2b,
    __half* __restrict__ C1, __half* __restrict__ C2, int M)
{
    __shared__ __nv_bfloat16 Ah[64][40];
    __shared__ __nv_bfloat16 Wh[32][264];

    const int tid = threadIdx.x, lane = tid & 31, wid = tid >> 5;
    const int wm = wid & 1;
    const int wn = wid >> 1;
    const int r0 = blockIdx.x * 64;

    float d[2][8][4];
    #pragma unroll
    for (int i = 0; i < 2; i++)
        #pragma unroll
        for (int j = 0; j < 8; j++)
            #pragma unroll
            for (int k = 0; k < 4; k++) d[i][j][k] = 0.f;

    for (int kt = 0; kt < 4; kt++) {
        if (RAW) {
            // A first (input x launch-ready), gridsync before W (split pending)
            #pragma unroll
            for (int i = 0; i < 2; i++) {
                int idx = tid + i * 256;
                int row = idx >> 3, q = idx & 7;
                float4 v = make_float4(0.f, 0.f, 0.f, 0.f);
                if (r0 + row < M)
                    v = *(const float4*)(Araw + (size_t)(r0 + row) * 128 + kt * 32 + q * 4);
                __nv_bfloat16 h[4];
                h[0] = __float2bfloat16(v.x); h[1] = __float2bfloat16(v.y);
                h[2] = __float2bfloat16(v.z); h[3] = __float2bfloat16(v.w);
                *(uint2*)&Ah[row][q * 4] = *(uint2*)h;
            }
            if (kt == 0) GRID_DEP_SYNC();
            #pragma unroll
            for (int i = 0; i < 4; i++) {
                int idx = tid + i * 256;
                int k = idx >> 5, q = idx & 31;
                const __nv_bfloat16* wp = (q < 16)
                    ? W1b + (size_t)(kt * 32 + k) * 128 + q * 8
                    : W2b + (size_t)(kt * 32 + k) * 128 + (q - 16) * 8;
                *(uint4*)&Wh[k][q * 8] = *(const uint4*)wp;
            }
        } else {
            // W first (ready), gridsync before A (pending hs)
            #pragma unroll
            for (int i = 0; i < 4; i++) {
                int idx = tid + i * 256;
                int k = idx >> 5, q = idx & 31;
                const __nv_bfloat16* wp = (q < 16)
                    ? W1b + (size_t)(kt * 32 + k) * 128 + q * 8
                    : W2b + (size_t)(kt * 32 + k) * 128 + (q - 16) * 8;
                *(uint4*)&Wh[k][q * 8] = *(const uint4*)wp;
            }
            if (kt == 0) GRID_DEP_SYNC();
            {
                int idx = tid;                 // 256 uint4 = 64 rows x 4
                int row = idx >> 2, q = idx & 3;
                uint4 p = make_uint4(0u, 0u, 0u, 0u);
                if (r0 + row < M)
                    p = *(const uint4*)(Ab + (size_t)(r0 + row) * 128 + kt * 32 + q * 8);
                *(uint4*)&Ah[row][q * 8] = p;
            }
        }
        __syncthreads();

        #pragma unroll
        for (int k16 = 0; k16 < 2; k16++) {
            uint32_t af[2][4], bfr[8][2];
            #pragma unroll
            for (int mf = 0; mf < 2; mf++) {
                uint32_t addr = smem_u32(
                    &Ah[wm * 32 + mf * 16 + (lane & 15)][k16 * 16 + (lane >> 4) * 8]);
                ldsm_x4(af[mf][0], af[mf][1], af[mf][2], af[mf][3], addr);
            }
            #pragma unroll
            for (int nf = 0; nf < 8; nf++) {
                uint32_t addr = smem_u32(
                    &Wh[k16 * 16 + (lane & 15)][wn * 64 + nf * 8]);
                ldsm_x2_t(bfr[nf][0], bfr[nf][1], addr);
            }
            #pragma unroll
            for (int mf = 0; mf < 2; mf++)
                #pragma unroll
                for (int nf = 0; nf < 8; nf++)
                    mma_bf16c(d[mf][nf], af[mf], bfr[nf]);
        }
        __syncthreads();
    }

    const int g = lane >> 2, t = lane & 3;
    __half* Cp = (wn < 2) ? C1 : C2;
    int cbase = (wn < 2) ? wn * 64 : (wn - 2) * 64;
    #pragma unroll
    for (int mf = 0; mf < 2; mf++) {
        #pragma unroll
        for (int nf = 0; nf < 8; nf++) {
            int row0 = r0 + wm * 32 + mf * 16 + g;
            int col = cbase + nf * 8 + t * 2;
            if (row0 < M)
                *(__half2*)(Cp + (size_t)row0 * 128 + col) =
                    __floats2half2_rn(d[mf][nf][0], d[mf][nf][1]);
            if (row0 + 8 < M)
                *(__half2*)(Cp + (size_t)(row0 + 8) * 128 + col) =
                    __floats2half2_rn(d[mf][nf][2], d[mf][nf][3]);
        }
    }
}

// ================= TC dual GEMM layer 3 (N=40 padded to 64, fp32 out) =======
__global__ __launch_bounds__(256, 2) void k_gemm_tc3(
    const __nv_bfloat16* __restrict__ Ab, const __nv_bfloat16* __restrict__ W3b,
    float* __restrict__ C1, float* __restrict__ C2, int M)
{
    __shared__ __nv_bfloat16 Ah[64][40];
    __shared__ __nv_bfloat16 Wh[32][136];

    const int tid = threadIdx.x, lane = tid & 31, wid = tid >> 5;
    const int wm = wid & 1;
    const int wn = wid >> 1;
    const int r0 = blockIdx.x * 64;

    float d[2][4][4];
    #pragma unroll
    for (int i = 0; i < 2; i++)
        #pragma unroll
        for (int j = 0; j < 4; j++)
            #pragma unroll
            for (int k = 0; k < 4; k++) d[i][j][k] = 0.f;

    for (int kt = 0; kt < 4; kt++) {
        // W first (ready), gridsync, then A (pending hs)
        #pragma unroll
        for (int i = 0; i < 2; i++) {
            int idx = tid + i * 256;
            int k = idx >> 4, q = idx & 15;
            const __nv_bfloat16* wp = W3b + ((q >= 8) ? 8192 : 0)
                                    + (size_t)(kt * 32 + k) * 64 + (q & 7) * 8;
            *(uint4*)&Wh[k][q * 8] = *(const uint4*)wp;
        }
        if (kt == 0) GRID_DEP_SYNC();
        {
            int idx = tid;
            int row = idx >> 2, q = idx & 3;
            uint4 p = make_uint4(0u, 0u, 0u, 0u);
            if (r0 + row < M)
                p = *(const uint4*)(Ab + (size_t)(r0 + row) * 128 + kt * 32 + q * 8);
            *(uint4*)&Ah[row][q * 8] = p;
        }
        __syncthreads();

        #pragma unroll
        for (int k16 = 0; k16 < 2; k16++) {
            uint32_t af[2][4], bfr[4][2];
            #pragma unroll
            for (int mf = 0; mf < 2; mf++) {
                uint32_t addr = smem_u32(
                    &Ah[wm * 32 + mf * 16 + (lane & 15)][k16 * 16 + (lane >> 4) * 8]);
                ldsm_x4(af[mf][0], af[mf][1], af[mf][2], af[mf][3], addr);
            }
            #pragma unroll
            for (int nf = 0; nf < 4; nf++) {
                uint32_t addr = smem_u32(
                    &Wh[k16 * 16 + (lane & 15)][wn * 32 + nf * 8]);
                ldsm_x2_t(bfr[nf][0], bfr[nf][1], addr);
            }
            #pragma unroll
            for (int mf = 0; mf < 2; mf++)
                #pragma unroll
                for (int nf = 0; nf < 4; nf++)
                    mma_bf16c(d[mf][nf], af[mf], bfr[nf]);
        }
        __syncthreads();
    }

    const int g = lane >> 2, t = lane & 3;
    float* Cp = (wn < 2) ? C1 : C2;
    int cbase = (wn & 1) * 32;
    #pragma unroll
    for (int mf = 0; mf < 2; mf++) {
        #pragma unroll
        for (int nf = 0; nf < 4; nf++) {
            int row0 = r0 + wm * 32 + mf * 16 + g;
            int col = cbase + nf * 8 + t * 2;
            if (col >= 40) continue;
            if (row0 < M)
                *(float2*)(Cp + (size_t)row0 * 40 + col) = make_float2(d[mf][nf][0], d[mf][nf][1]);
            if (row0 + 8 < M)
                *(float2*)(Cp + (size_t)(row0 + 8) * 40 + col) = make_float2(d[mf][nf][2], d[mf][nf][3]);
        }
    }
}

// ================= node aggregation (H=4, F=32), half2 math, 2 edges/warp ===
// Output: plain bf16 hidden features.
__global__ __launch_bounds__(256) void k_node_h4(
    const uint4* __restrict__ glh, const uint4* __restrict__ grh,
    const float* __restrict__ att,
    const int* __restrict__ off, const int* __restrict__ deg,
    const int* __restrict__ eidx, __nv_bfloat16* __restrict__ houtb, int mode)
{
    int n = blockIdx.x * 8 + (threadIdx.x >> 5);
    if (n >= N_NODES) return;
    int lane = threadIdx.x & 31;
    int sub = lane >> 4;
    int ll = lane & 15;

    // att is a launch-ready input — load before the dependency sync
    float4 t0 = __ldg((const float4*)att + 2 * ll);
    float4 t1 = __ldg((const float4*)att + 2 * ll + 1);
    __half2 t2[4];
    t2[0] = __floats2half2_rn(t0.x, t0.y); t2[1] = __floats2half2_rn(t0.z, t0.w);
    t2[2] = __floats2half2_rn(t1.x, t1.y); t2[3] = __floats2half2_rn(t1.z, t1.w);
    const __half2 slope2 = __floats2half2_rn(SLOPE, SLOPE);

    GRID_DEP_SYNC();

    uint4 braw = grh[(size_t)n * 16 + ll];
    __half2 b2[4];
    b2[0] = *(__half2*)&braw.x; b2[1] = *(__half2*)&braw.y;
    b2[2] = *(__half2*)&braw.z; b2[3] = *(__half2*)&braw.w;

    float f[8];
    #pragma unroll
    for (int i = 0; i < 8; i++) f[i] = 0.f;
    float dw = 0.f;

    int start = off[n], cnt = deg[n];
    for (int base = 0; base < cnt; base += 32) {
        int rem = cnt - base;
        int m = rem < 32 ? rem : 32;
        int eld = (lane < m) ? __ldg(&eidx[start + base + lane]) : 0;
        int hm = (m + 1) >> 1;
        for (int j = 0; j < hm; j++) {
            int idx = 2 * j + sub;
            int s = __shfl_sync(0xffffffffu, eld, idx);
            uint4 araw = __ldg(&glh[(size_t)s * 16 + ll]);
            __half2 a2[4];
            a2[0] = *(__half2*)&araw.x; a2[1] = *(__half2*)&araw.y;
            a2[2] = *(__half2*)&araw.z; a2[3] = *(__half2*)&araw.w;

            __half2 acc = __floats2half2_rn(0.f, 0.f);
            #pragma unroll
            for (int i = 0; i < 4; i++) {
                __half2 s2 = __hadd2(a2[i], b2[i]);
                __half2 e2 = __hmax2(s2, __hmul2(s2, slope2));
                acc = __hfma2(e2, t2[i], acc);
            }
            float2 pf = __half22float2(acc);
            float p = pf.x + pf.y;
            p += __shfl_xor_sync(0xffffffffu, p, 2);
            p += __shfl_xor_sync(0xffffffffu, p, 1);
            float w = (idx < m) ? __expf(p) : 0.f;

            #pragma unroll
            for (int i = 0; i < 4; i++) {
                float2 af = __half22float2(a2[i]);
                f[2 * i]     += w * af.x;
                f[2 * i + 1] += w * af.y;
            }
            dw += w;
        }
    }

    #pragma unroll
    for (int i = 0; i < 8; i++) f[i] += __shfl_xor_sync(0xffffffffu, f[i], 16);
    dw += __shfl_xor_sync(0xffffffffu, dw, 16);

    if (sub == 0) {
        float inv = 1.0f / (dw + 1e-16f);
        __nv_bfloat16 ob[8];
        #pragma unroll
        for (int i = 0; i < 8; i++) {
            float v = f[i] * inv;
            if (mode == 1) v = v > 0.f ? v : expm1f(v);
            else           v = fmaxf(v, 0.f);
            ob[i] = __float2bfloat16(v);
        }
        *(uint4*)(houtb + (size_t)n * 128 + 8 * ll) = *(uint4*)ob;
    }
}

// ================= node layer 3 + log_softmax (H=1, F=40, fp32) =============
__global__ __launch_bounds__(256) void k_node_h1_lsm(
    const float4* __restrict__ gl4, const float4* __restrict__ gr4,
    const float* __restrict__ att,
    const int* __restrict__ off, const int* __restrict__ deg,
    const int* __restrict__ eidx, float* __restrict__ out)
{
    int n = blockIdx.x * 8 + (threadIdx.x >> 5);
    if (n >= N_NODES) return;
    int lane = threadIdx.x & 31;
    int sub = lane >> 4;
    int ll = lane & 15;

    float4 t = make_float4(0.f, 0.f, 0.f, 0.f);
    if (ll < 10) t = __ldg(&((const float4*)att)[ll]);

    GRID_DEP_SYNC();

    float4 b = make_float4(0.f, 0.f, 0.f, 0.f);
    if (ll < 10) b = gr4[(size_t)n * 10 + ll];

    float ax = 0.f, ay = 0.f, az = 0.f, aw = 0.f, dw = 0.f;

    int start = off[n], cnt = deg[n];
    for (int base = 0; base < cnt; base += 32) {
        int rem = cnt - base;
        int m = rem < 32 ? rem : 32;
        int eld = (lane < m) ? __ldg(&eidx[start + base + lane]) : 0;
        int hm = (m + 1) >> 1;
        for (int j = 0; j < hm; j++) {
            int idx = 2 * j + sub;
            int s = __shfl_sync(0xffffffffu, eld, idx);
            float4 a = make_float4(0.f, 0.f, 0.f, 0.f);
            float p = 0.f;
            if (ll < 10) {
                a = __ldg(&gl4[(size_t)s * 10 + ll]);
                float vx = a.x + b.x; vx = vx > 0.f ? vx : SLOPE * vx;
                float vy = a.y + b.y; vy = vy > 0.f ? vy : SLOPE * vy;
                float vz = a.z + b.z; vz = vz > 0.f ? vz : SLOPE * vz;
                float vw = a.w + b.w; vw = vw > 0.f ? vw : SLOPE * vw;
                p = vx * t.x + vy * t.y + vz * t.z + vw * t.w;
            }
            p += __shfl_xor_sync(0xffffffffu, p, 8, 16);
            p += __shfl_xor_sync(0xffffffffu, p, 4, 16);
            p += __shfl_xor_sync(0xffffffffu, p, 2, 16);
            p += __shfl_xor_sync(0xffffffffu, p, 1, 16);
            float w = (idx < m) ? __expf(p) : 0.f;
            ax += w * a.x; ay += w * a.y; az += w * a.z; aw += w * a.w;
            dw += w;
        }
    }

    ax += __shfl_xor_sync(0xffffffffu, ax, 16);
    ay += __shfl_xor_sync(0xffffffffu, ay, 16);
    az += __shfl_xor_sync(0xffffffffu, az, 16);
    aw += __shfl_xor_sync(0xffffffffu, aw, 16);
    dw += __shfl_xor_sync(0xffffffffu, dw, 16);

    float inv = 1.0f / (dw + 1e-16f);
    float4 v = make_float4(ax * inv, ay * inv, az * inv, aw * inv);

    float mx = (ll < 10) ? fmaxf(fmaxf(v.x, v.y), fmaxf(v.z, v.w)) : -FLT_MAX;
    #pragma unroll
    for (int o = 8; o > 0; o >>= 1) mx = fmaxf(mx, __shfl_xor_sync(0xffffffffu, mx, o, 16));
    float ss = (ll < 10)
        ? (expf(v.x - mx) + expf(v.y - mx) + expf(v.z - mx) + expf(v.w - mx)) : 0.f;
    #pragma unroll
    for (int o = 8; o > 0; o >>= 1) ss += __shfl_xor_sync(0xffffffffu, ss, o, 16);
    float lse = mx + logf(ss);
    if (sub == 0 && ll < 10) {
        float4 r = make_float4(v.x - lse, v.y - lse, v.z - lse, v.w - lse);
        *(float4*)(out + (size_t)n * 40 + 4 * ll) = r;
    }
}

// ---------------- host -------------------------------------------------------
extern "C" void kernel_launch(void* const* d_in, const int* in_sizes, int n_in,
                              void* d_out, int out_size)
{
    const float* x    = (const float*)d_in[0];
    const float* Wl1  = (const float*)d_in[1];
    const float* Wr1  = (const float*)d_in[2];
    const float* att1 = (const float*)d_in[3];
    const float* Wl2  = (const float*)d_in[4];
    const float* Wr2  = (const float*)d_in[5];
    const float* att2 = (const float*)d_in[6];
    const float* Wl3  = (const float*)d_in[7];
    const float* Wr3  = (const float*)d_in[8];
    const float* att3 = (const float*)d_in[9];
    const int*   ei   = (const int*)d_in[10];
    const int* src = ei;
    const int* dst = ei + N_EDGES;
    float* out = (float*)d_out;

    float *gl, *gr;
    __nv_bfloat16 *hsb, *wsb, *w3sb;
    int *deg, *off, *cur, *bsum, *eidx;
    cudaGetSymbolAddress((void**)&gl,   g_gl);
    cudaGetSymbolAddress((void**)&gr,   g_gr);
    cudaGetSymbolAddress((void**)&hsb,  g_hsb);
    cudaGetSymbolAddress((void**)&wsb,  g_wsb);
    cudaGetSymbolAddress((void**)&w3sb, g_w3sb);
    cudaGetSymbolAddress((void**)&deg,  g_deg);
    cudaGetSymbolAddress((void**)&off,  g_off);
    cudaGetSymbolAddress((void**)&cur,  g_cur);
    cudaGetSymbolAddress((void**)&bsum, g_bsum);
    cudaGetSymbolAddress((void**)&eidx, g_eidx);

    __half* glh = (__half*)gl;
    __half* grh = (__half*)gr;

    const int GB = (N_NODES + 63) / 64;
    const int NB = (N_NODES + 7) / 8;
    const int NSCAN = (N_NODES + 1023) / 1024;

    static cudaStream_t s2 = nullptr;
    static cudaEvent_t evFork = nullptr, evJoin = nullptr;
    if (!s2) {
        cudaStreamCreateWithFlags(&s2, cudaStreamNonBlocking);
        cudaEventCreateWithFlags(&evFork, cudaEventDisableTiming);
        cudaEventCreateWithFlags(&evJoin, cudaEventDisableTiming);
    }

    cudaLaunchAttribute pdlAttr;
    pdlAttr.id = cudaLaunchAttributeProgrammaticStreamSerialization;
    pdlAttr.val.programmaticStreamSerializationAllowed = 1;
    cudaLaunchConfig_t cfg = {};
    cfg.blockDim = {256, 1, 1};
    cfg.stream = 0;
    cfg.attrs = &pdlAttr;
    cfg.numAttrs = 1;

    // ---- fork: CSR build on s2, concurrent with weight cvt + layer-1 GEMM
    cudaEventRecord(evFork, 0);
    cudaStreamWaitEvent(s2, evFork, 0);
    cudaMemsetAsync(deg, 0, N_NODES * sizeof(int), s2);
    k_hist<<<(N_EDGES + 255) / 256, 256, 0, s2>>>(dst, deg);
    k_scan_part<<<NSCAN, 1024, 0, s2>>>(deg, off, bsum);
    k_scan_add<<<(N_NODES + 255) / 256, 256, 0, s2>>>(off, cur, bsum);
    k_scatter<<<(N_EDGES + 255) / 256, 256, 0, s2>>>(src, dst, cur, eidx);
    cudaEventRecord(evJoin, s2);

    // main stream: weight cvt, then layer-1 GEMM (PDL: A=x ready, W pending)
    k_split_w<<<80, 256>>>(Wl1, Wr1, Wl2, Wr2, wsb, Wl3, Wr3, w3sb);
    {
        cfg.gridDim = {(unsigned)GB, 1, 1};
        const __nv_bfloat16* ab = nullptr;
        cudaLaunchKernelEx(&cfg, k_gemm_tc2<true>, ab, x,
                           (const __nv_bfloat16*)(wsb + 0 * 16384),
                           (const __nv_bfloat16*)(wsb + 1 * 16384),
                           glh, grh, (int)N_NODES);
    }
    cudaStreamWaitEvent(0, evJoin, 0);

    // ---- Layer 1 aggregate (PDL) ----
    {
        cfg.gridDim = {(unsigned)NB, 1, 1};
        cudaLaunchKernelEx(&cfg, k_node_h4,
                           (const uint4*)glh, (const uint4*)grh, att1,
                           (const int*)off, (const int*)deg, (const int*)eidx,
                           hsb, 1);
    }
    // ---- Layer 2 ----
    {
        cfg.gridDim = {(unsigned)GB, 1, 1};
        const float* araw = nullptr;
        cudaLaunchKernelEx(&cfg, k_gemm_tc2<false>, (const __nv_bfloat16*)hsb, araw,
                           (const __nv_bfloat16*)(wsb + 2 * 16384),
                           (const __nv_bfloat16*)(wsb + 3 * 16384),
                           glh, grh, (int)N_NODES);
    }
    {
        cfg.gridDim = {(unsigned)NB, 1, 1};
        cudaLaunchKernelEx(&cfg, k_node_h4,
                           (const uint4*)glh, (const uint4*)grh, att2,
                           (const int*)off, (const int*)deg, (const int*)eidx,
                           hsb, 2);
    }
    // ---- Layer 3 (TC GEMM, fp32 out; fused aggregate + log_softmax) ----
    {
        cfg.gridDim = {(unsigned)GB, 1, 1};
        cudaLaunchKernelEx(&cfg, k_gemm_tc3, (const __nv_bfloat16*)hsb,
                           (const __nv_bfloat16*)w3sb, gl, gr, (int)N_NODES);
    }
    {
        cfg.gridDim = {(unsigned)NB, 1, 1};
        cudaLaunchKernelEx(&cfg, k_node_h1_lsm,
                           (const float4*)gl, (const float4*)gr, att3,
                           (const int*)off, (const int*)deg, (const int*)eidx,
                           out);
    }
}